// round 2
// baseline (speedup 1.0000x reference)
#include <cuda_runtime.h>
#include <math.h>

#define NB 16
#define NA 720
#define ND 1024
#define NH 512
#define NW 512
#define PI_F 3.14159265358979323846f

// Filtered sinogram, batch-interleaved: [g = b/4][a][d] -> float4 over 4 batches.
// 4 groups * 720 * 1024 * 16B = 47.2 MB (fits in 126MB L2).
__device__ float4 g_fil4[4 * NA * ND];

__device__ __forceinline__ float2 cmulf(float2 a, float2 b) {
    return make_float2(a.x * b.x - a.y * b.y, a.x * b.y + a.y * b.x);
}

// Packed f32x2 helpers (sm_10x FFMA2 path)
__device__ __forceinline__ unsigned long long ffma2(
    unsigned long long a, unsigned long long b, unsigned long long c) {
    unsigned long long d;
    asm("fma.rn.f32x2 %0, %1, %2, %3;" : "=l"(d) : "l"(a), "l"(b), "l"(c));
    return d;
}
__device__ __forceinline__ unsigned long long pack2(float lo, float hi) {
    unsigned long long d;
    asm("mov.b64 %0, {%1, %2};" : "=l"(d) : "f"(lo), "f"(hi));
    return d;
}
__device__ __forceinline__ void unpack2(unsigned long long v, float& lo, float& hi) {
    asm("mov.b64 {%0, %1}, %2;" : "=f"(lo), "=f"(hi) : "l"(v));
}

// -------------------------------------------------------------------------
// Kernel 1: ramp filter. Real-pair trick: the filter is real & even, so
// filtering (u + i*v) gives filtered(u) + i*filtered(v) exactly. One block
// filters TWO batch rows (2m, 2m+1) at angle a in one complex FFT, and the
// complex result (re,im) is exactly the (2m,2m+1) slot pair of the
// interleaved float4 layout -> direct float2 store, no transpose pass.
// -------------------------------------------------------------------------
__global__ __launch_bounds__(512) void fbp_filter_kernel(
    const float* __restrict__ sino, const float* __restrict__ filt)
{
    __shared__ float2 bufA[ND];
    __shared__ float2 bufB[ND];
    __shared__ float2 tw[ND / 2];   // exp(-2*pi*i*k/N), k in [0,512)

    const int a = blockIdx.x;       // angle
    const int m = blockIdx.y;       // batch pair: rows 2m and 2m+1
    const int tid = threadIdx.x;    // 0 .. 511

    const float* u = sino + ((size_t)(2 * m) * NA + a) * ND;
    const float* v = sino + ((size_t)(2 * m + 1) * NA + a) * ND;

    bufA[tid]       = make_float2(u[tid],       v[tid]);
    bufA[tid + 512] = make_float2(u[tid + 512], v[tid + 512]);
    {
        float sv, cv;
        sincosf((-2.0f * PI_F / ND) * (float)tid, &sv, &cv);
        tw[tid] = make_float2(cv, sv);
    }
    __syncthreads();

    float2* x = bufA;
    float2* y = bufB;

    // Forward FFT (Stockham)
    #pragma unroll
    for (int stage = 0; stage < 10; ++stage) {
        const int s  = 1 << stage;
        const int q  = tid & (s - 1);
        const int ps = tid - q;
        float2 aa = x[tid];
        float2 bb = x[tid + 512];
        float2 w = tw[ps];
        y[2 * ps + q]     = make_float2(aa.x + bb.x, aa.y + bb.y);
        y[2 * ps + s + q] = cmulf(make_float2(aa.x - bb.x, aa.y - bb.y), w);
        __syncthreads();
        float2* t = x; x = y; y = t;
    }

    // Multiply by the (real, even) ramp filter
    {
        float f0 = filt[tid], f1 = filt[tid + 512];
        float2 aa = x[tid];       aa.x *= f0; aa.y *= f0; x[tid]       = aa;
        float2 bb = x[tid + 512]; bb.x *= f1; bb.y *= f1; x[tid + 512] = bb;
    }
    __syncthreads();

    // Inverse FFT (conjugated twiddles), scale 1/N at the end
    #pragma unroll
    for (int stage = 0; stage < 10; ++stage) {
        const int s  = 1 << stage;
        const int q  = tid & (s - 1);
        const int ps = tid - q;
        float2 aa = x[tid];
        float2 bb = x[tid + 512];
        float2 w = tw[ps]; w.y = -w.y;
        y[2 * ps + q]     = make_float2(aa.x + bb.x, aa.y + bb.y);
        y[2 * ps + s + q] = cmulf(make_float2(aa.x - bb.x, aa.y - bb.y), w);
        __syncthreads();
        float2* t = x; x = y; y = t;
    }

    // Store (re, im) = filtered rows (2m, 2m+1) into interleaved layout:
    // float4 element e = (g*NA + a)*ND + d holds batches 4g..4g+3;
    // pair m writes the float2 at byte offset 8*(m&1).
    const float invN = 1.0f / (float)ND;
    float2* f2 = (float2*)g_fil4;
    const size_t base2 = 2 * (((size_t)(m >> 1) * NA + a) * (size_t)ND) + (m & 1);
    float2 r0 = x[tid];
    float2 r1 = x[tid + 512];
    f2[base2 + 2 * (size_t)tid]         = make_float2(r0.x * invN, r0.y * invN);
    f2[base2 + 2 * (size_t)(tid + 512)] = make_float2(r1.x * invN, r1.y * invN);
}

// -------------------------------------------------------------------------
// Kernel 2: backprojection. Each thread: one pixel, 8 batches (2 float4
// groups). Per angle: 4 LDG.128 + 8 FFMA2. Warp footprint 8x4 pixels to
// minimize detector-bin span (fewer L1 lines per wavefront).
// t in [150.2, 872.8] always -> no bounds checks (proof: |px|,|py|<=255.5).
// -------------------------------------------------------------------------
__global__ __launch_bounds__(256) void fbp_backproj_kernel(float* __restrict__ out)
{
    __shared__ float2 cs[NA];

    const int tid = threadIdx.x;
    for (int i = tid; i < NA; i += 256) {
        float sv, cv;
        sincosf((PI_F / (float)NA) * (float)i, &sv, &cv);
        cs[i] = make_float2(cv, sv);
    }
    __syncthreads();

    const int wrp  = tid >> 5;
    const int lane = tid & 31;
    const int x = (blockIdx.x << 4) + (lane & 7) + ((wrp & 1) << 3);
    const int y = (blockIdx.y << 4) + (lane >> 3) + ((wrp >> 1) << 2);
    const float px = (float)x - 0.5f * (float)(NW - 1);
    const float py = (float)y - 0.5f * (float)(NH - 1);

    const int g0 = blockIdx.z * 2;            // groups g0, g0+1 -> batches 8z..8z+7
    const ulonglong2* r0base = (const ulonglong2*)(g_fil4 + (size_t)g0 * NA * ND);
    const ulonglong2* r1base = r0base + NA * ND;

    unsigned long long acc00 = 0ull, acc01 = 0ull;   // group g0: (b0,b1),(b2,b3)
    unsigned long long acc10 = 0ull, acc11 = 0ull;   // group g0+1

    #pragma unroll 2
    for (int a = 0; a < NA; ++a) {
        float2 csa = cs[a];
        float t  = fmaf(px, csa.x, fmaf(py, csa.y, 0.5f * (float)(ND - 1)));
        float fi = floorf(t);
        int   i0 = (int)fi;
        float fw  = t - fi;
        float fww = 1.0f - fw;
        unsigned long long w2  = pack2(fw,  fw);
        unsigned long long ww2 = pack2(fww, fww);

        const int off = a * ND + i0;
        ulonglong2 a0 = r0base[off];
        ulonglong2 a1 = r0base[off + 1];
        ulonglong2 b0 = r1base[off];
        ulonglong2 b1 = r1base[off + 1];

        acc00 = ffma2(ww2, a0.x, ffma2(w2, a1.x, acc00));
        acc01 = ffma2(ww2, a0.y, ffma2(w2, a1.y, acc01));
        acc10 = ffma2(ww2, b0.x, ffma2(w2, b1.x, acc10));
        acc11 = ffma2(ww2, b0.y, ffma2(w2, b1.y, acc11));
    }

    const float scale = PI_F / (float)NA;
    const size_t pix = (size_t)y * NW + x;
    const size_t HW = (size_t)NH * NW;
    float o0, o1;

    float* dst = out + (size_t)(4 * g0) * HW + pix;
    unpack2(acc00, o0, o1); dst[0 * HW] = o0 * scale; dst[1 * HW] = o1 * scale;
    unpack2(acc01, o0, o1); dst[2 * HW] = o0 * scale; dst[3 * HW] = o1 * scale;
    unpack2(acc10, o0, o1); dst[4 * HW] = o0 * scale; dst[5 * HW] = o1 * scale;
    unpack2(acc11, o0, o1); dst[6 * HW] = o0 * scale; dst[7 * HW] = o1 * scale;
}

extern "C" void kernel_launch(void* const* d_in, const int* in_sizes, int n_in,
                              void* d_out, int out_size)
{
    const float* sino = (const float*)d_in[0];   // (16, 720, 1024) fp32
    const float* filt = (const float*)d_in[1];   // (1024,) fp32
    float* out = (float*)d_out;                  // (16, 512, 512) fp32

    dim3 fgrid(NA, NB / 2);
    fbp_filter_kernel<<<fgrid, 512>>>(sino, filt);

    dim3 bgrid(NW / 16, NH / 16, 2);
    fbp_backproj_kernel<<<bgrid, 256>>>(out);
}

// round 3
// speedup vs baseline: 1.4441x; 1.4441x over previous
#include <cuda_runtime.h>
#include <cuda_fp16.h>
#include <math.h>

#define NB 16
#define NA 720
#define ND 1024
#define NH 512
#define NW 512
#define PI_F 3.14159265358979323846f

// Filtered sinogram in fp16 with precomputed forward differences.
// Layout: [g2 in 0..1][a][d] -> 32B record: 8 halfs v (batches 8*g2..8*g2+7),
//                               8 halfs d (= v[bin+1]-v[bin]).
// Total: 2*720*1024*32B = 47.2 MB (L2-resident).
__device__ uint4 g_fil[2 * NA * ND * 2];

__device__ __forceinline__ float2 cmulf(float2 a, float2 b) {
    return make_float2(a.x * b.x - a.y * b.y, a.x * b.y + a.y * b.x);
}
__device__ __forceinline__ unsigned int h2_as_u32(__half2 h) {
    return *reinterpret_cast<unsigned int*>(&h);
}

// -------------------------------------------------------------------------
// Kernel 1: ramp filter via complex-pair Stockham FFT (filter is real&even,
// so FFT(u+iv)*f -> re=filt(u), im=filt(v) exactly). Block = (angle a,
// batch pair m=(2m,2m+1)). Output: fp16 {v,d} interleaved records.
// -------------------------------------------------------------------------
__global__ __launch_bounds__(512) void fbp_filter_kernel(
    const float* __restrict__ sino, const float* __restrict__ filt)
{
    __shared__ float2 bufA[ND];
    __shared__ float2 bufB[ND];
    __shared__ float2 tw[ND / 2];

    const int a = blockIdx.x;
    const int m = blockIdx.y;       // batches 2m, 2m+1
    const int tid = threadIdx.x;

    const float* u = sino + ((size_t)(2 * m) * NA + a) * ND;
    const float* v = sino + ((size_t)(2 * m + 1) * NA + a) * ND;

    bufA[tid]       = make_float2(u[tid],       v[tid]);
    bufA[tid + 512] = make_float2(u[tid + 512], v[tid + 512]);
    {
        float sv, cv;
        sincosf((-2.0f * PI_F / ND) * (float)tid, &sv, &cv);
        tw[tid] = make_float2(cv, sv);
    }
    __syncthreads();

    float2* x = bufA;
    float2* y = bufB;

    #pragma unroll
    for (int stage = 0; stage < 10; ++stage) {
        const int s  = 1 << stage;
        const int q  = tid & (s - 1);
        const int ps = tid - q;
        float2 aa = x[tid];
        float2 bb = x[tid + 512];
        float2 w = tw[ps];
        y[2 * ps + q]     = make_float2(aa.x + bb.x, aa.y + bb.y);
        y[2 * ps + s + q] = cmulf(make_float2(aa.x - bb.x, aa.y - bb.y), w);
        __syncthreads();
        float2* t = x; x = y; y = t;
    }
    {
        float f0 = filt[tid], f1 = filt[tid + 512];
        float2 aa = x[tid];       aa.x *= f0; aa.y *= f0; x[tid]       = aa;
        float2 bb = x[tid + 512]; bb.x *= f1; bb.y *= f1; x[tid + 512] = bb;
    }
    __syncthreads();
    #pragma unroll
    for (int stage = 0; stage < 10; ++stage) {
        const int s  = 1 << stage;
        const int q  = tid & (s - 1);
        const int ps = tid - q;
        float2 aa = x[tid];
        float2 bb = x[tid + 512];
        float2 w = tw[ps]; w.y = -w.y;
        y[2 * ps + q]     = make_float2(aa.x + bb.x, aa.y + bb.y);
        y[2 * ps + s + q] = cmulf(make_float2(aa.x - bb.x, aa.y - bb.y), w);
        __syncthreads();
        float2* t = x; x = y; y = t;
    }

    // Store fp16 {v,d}. Pair p occupies u32 slot p (v) and 4+p (d) of each
    // 8-u32 bin record. low half = batch 2m (re), high = 2m+1 (im).
    const float invN = 1.0f / (float)ND;
    const int g2 = m >> 2;
    const int p  = m & 3;
    unsigned int* out32 = (unsigned int*)g_fil;
    const size_t base_u = ((size_t)(g2 * NA + a) * ND) * 8;

    // bin = tid
    {
        float2 c  = x[tid];
        float2 cn = x[tid + 1];
        __half2 hv = __floats2half2_rn(c.x * invN, c.y * invN);
        __half2 hd = __floats2half2_rn((cn.x - c.x) * invN, (cn.y - c.y) * invN);
        out32[base_u + (size_t)tid * 8 + p]     = h2_as_u32(hv);
        out32[base_u + (size_t)tid * 8 + 4 + p] = h2_as_u32(hd);
    }
    // bin = tid + 512
    {
        float2 c  = x[tid + 512];
        float2 cn = (tid < 511) ? x[tid + 513] : c;   // d(1023)=0, never read
        __half2 hv = __floats2half2_rn(c.x * invN, c.y * invN);
        __half2 hd = __floats2half2_rn((cn.x - c.x) * invN, (cn.y - c.y) * invN);
        out32[base_u + (size_t)(tid + 512) * 8 + p]     = h2_as_u32(hv);
        out32[base_u + (size_t)(tid + 512) * 8 + 4 + p] = h2_as_u32(hd);
    }
}

// -------------------------------------------------------------------------
// Kernel 2: backprojection. 1 pixel x 8 batches per thread. Per angle:
// 2x LDG.128 (one 32B {v,d} record), 4 HFMA2 + 4 HADD2 fp16 lerp+acc.
// fp16 accumulators flushed to fp32 every 8 angles (keeps quarter-rate
// cvt off the critical path AND bounds fp16 accumulation error).
// t in [150.2, 872.8] always -> no bounds checks.
// -------------------------------------------------------------------------
__global__ __launch_bounds__(256) void fbp_backproj_kernel(float* __restrict__ out)
{
    __shared__ float2 cs[NA];

    const int tid = threadIdx.x;
    for (int i = tid; i < NA; i += 256) {
        float sv, cv;
        sincosf((PI_F / (float)NA) * (float)i, &sv, &cv);
        cs[i] = make_float2(cv, sv);
    }
    __syncthreads();

    const int wrp  = tid >> 5;
    const int lane = tid & 31;
    const int x = (blockIdx.x << 4) + (lane & 7) + ((wrp & 1) << 3);
    const int y = (blockIdx.y << 4) + (lane >> 3) + ((wrp >> 1) << 2);
    const float px = (float)x - 0.5f * (float)(NW - 1);
    const float py = (float)y - 0.5f * (float)(NH - 1);

    const int g2 = blockIdx.z;                       // batches 8*g2 .. 8*g2+7
    const uint4* __restrict__ base = g_fil + (size_t)g2 * NA * ND * 2;

    float acc[8];
    #pragma unroll
    for (int j = 0; j < 8; ++j) acc[j] = 0.0f;

    for (int a0 = 0; a0 < NA; a0 += 8) {
        __half2 h0 = __float2half2_rn(0.0f);
        __half2 h1 = h0, h2 = h0, h3 = h0;

        #pragma unroll
        for (int k = 0; k < 8; ++k) {
            const int a = a0 + k;
            float2 csa = cs[a];
            float t  = fmaf(px, csa.x, fmaf(py, csa.y, 0.5f * (float)(ND - 1)));
            float fi = floorf(t);
            int   i0 = (int)fi;
            __half2 w2 = __float2half2_rn(t - fi);

            const uint4* rec = base + ((size_t)(a * ND + i0) << 1);
            uint4 v = rec[0];
            uint4 d = rec[1];

            __half2 v0 = *reinterpret_cast<__half2*>(&v.x);
            __half2 v1 = *reinterpret_cast<__half2*>(&v.y);
            __half2 v2 = *reinterpret_cast<__half2*>(&v.z);
            __half2 v3 = *reinterpret_cast<__half2*>(&v.w);
            __half2 d0 = *reinterpret_cast<__half2*>(&d.x);
            __half2 d1 = *reinterpret_cast<__half2*>(&d.y);
            __half2 d2 = *reinterpret_cast<__half2*>(&d.z);
            __half2 d3 = *reinterpret_cast<__half2*>(&d.w);

            h0 = __hadd2(h0, __hfma2(w2, d0, v0));
            h1 = __hadd2(h1, __hfma2(w2, d1, v1));
            h2 = __hadd2(h2, __hfma2(w2, d2, v2));
            h3 = __hadd2(h3, __hfma2(w2, d3, v3));
        }

        acc[0] += __low2float(h0);  acc[1] += __high2float(h0);
        acc[2] += __low2float(h1);  acc[3] += __high2float(h1);
        acc[4] += __low2float(h2);  acc[5] += __high2float(h2);
        acc[6] += __low2float(h3);  acc[7] += __high2float(h3);
    }

    const float scale = PI_F / (float)NA;
    const size_t pix = (size_t)y * NW + x;
    const size_t HW = (size_t)NH * NW;
    float* dst = out + (size_t)(8 * g2) * HW + pix;
    #pragma unroll
    for (int j = 0; j < 8; ++j)
        dst[(size_t)j * HW] = acc[j] * scale;
}

extern "C" void kernel_launch(void* const* d_in, const int* in_sizes, int n_in,
                              void* d_out, int out_size)
{
    const float* sino = (const float*)d_in[0];   // (16, 720, 1024) fp32
    const float* filt = (const float*)d_in[1];   // (1024,) fp32
    float* out = (float*)d_out;                  // (16, 512, 512) fp32

    dim3 fgrid(NA, NB / 2);
    fbp_filter_kernel<<<fgrid, 512>>>(sino, filt);

    dim3 bgrid(NW / 16, NH / 16, 2);
    fbp_backproj_kernel<<<bgrid, 256>>>(out);
}